// round 1
// baseline (speedup 1.0000x reference)
#include <cuda_runtime.h>
#include <math.h>

#define LEVELS 16
#define TABLE_SIZE 524288
#define HMASK (TABLE_SIZE - 1)
#define NPTS 1048576
#define PRIME 2654435761u
#define THREADS 256

struct ResArr { float r[LEVELS]; };

__global__ __launch_bounds__(THREADS)
void hashenc_kernel(const float* __restrict__ x,
                    const float2* __restrict__ tables,
                    float* __restrict__ out,
                    ResArr res)
{
    int n = blockIdx.x * blockDim.x + threadIdx.x;
    float2 p = reinterpret_cast<const float2*>(x)[n];

    float acc0[LEVELS];
    float acc1[LEVELS];

#pragma unroll
    for (int l = 0; l < LEVELS; ++l) {
        float r  = res.r[l];
        float sx = p.x * r;
        float sy = p.y * r;
        float gxf = floorf(sx);
        float gyf = floorf(sy);
        float fx = sx - gxf;          // |sx - gx|   (corner bx=0)
        float fy = sy - gyf;
        float ox = 1.0f - fx;         // |sx - (gx+1)| (corner bx=1)
        float oy = 1.0f - fy;

        unsigned gx = (unsigned)(int)gxf;
        unsigned gy = (unsigned)(int)gyf;
        unsigned hy0 = gy * PRIME;    // prime_x == 1, so hash = cx ^ (cy*PRIME)
        unsigned hy1 = hy0 + PRIME;   // (gy+1)*PRIME

        unsigned i00 = ( gx        ^ hy0) & HMASK;
        unsigned i10 = ((gx + 1u)  ^ hy0) & HMASK;
        unsigned i01 = ( gx        ^ hy1) & HMASK;
        unsigned i11 = ((gx + 1u)  ^ hy1) & HMASK;

        const float2* t = tables + (size_t)l * TABLE_SIZE;
        float2 f00 = __ldg(t + i00);
        float2 f10 = __ldg(t + i10);
        float2 f01 = __ldg(t + i01);
        float2 f11 = __ldg(t + i11);

        // corner order c = (0,0),(1,0),(0,1),(1,1); weight = |sx-cx|*|sy-cy|
        float w00 = fx * fy;
        float w10 = ox * fy;
        float w01 = fx * oy;
        float w11 = ox * oy;

        acc0[l] = ((w00 * f00.x + w10 * f10.x) + (w01 * f01.x + w11 * f11.x));
        acc1[l] = ((w00 * f00.y + w10 * f10.y) + (w01 * f01.y + w11 * f11.y));
    }

    // out[n, f*LEVELS + l], row = 32 floats = 128B, write as 8x float4
    float4* o = reinterpret_cast<float4*>(out + (size_t)n * (2 * LEVELS));
#pragma unroll
    for (int i = 0; i < 4; ++i)
        o[i] = make_float4(acc0[4*i], acc0[4*i+1], acc0[4*i+2], acc0[4*i+3]);
#pragma unroll
    for (int i = 0; i < 4; ++i)
        o[4 + i] = make_float4(acc1[4*i], acc1[4*i+1], acc1[4*i+2], acc1[4*i+3]);
}

extern "C" void kernel_launch(void* const* d_in, const int* in_sizes, int n_in,
                              void* d_out, int out_size)
{
    // Replicate numpy's exact float64 op sequence for _RESOLUTIONS on the host
    // (same container, same libm as the reference process):
    //   b = exp((log(512.) - log(16.)) / 15.);  res[l] = floor(16. * b**l)
    ResArr res;
    double b = exp((log(512.0) - log(16.0)) / 15.0);
    for (int l = 0; l < LEVELS; ++l) {
        double p;
        if (l == 0)      p = 1.0;     // npy_pow shortcut y==0
        else if (l == 1) p = b;       // pow(x,1) == x
        else             p = pow(b, (double)l);
        res.r[l] = (float)floor(16.0 * p);
    }

    const float*  x      = (const float*)d_in[0];
    const float2* tables = (const float2*)d_in[1];
    float*        out    = (float*)d_out;

    hashenc_kernel<<<NPTS / THREADS, THREADS>>>(x, tables, out, res);
}

// round 2
// speedup vs baseline: 1.1190x; 1.1190x over previous
#include <cuda_runtime.h>
#include <math.h>

#define LEVELS 16
#define TABLE_SIZE 524288
#define HMASK (TABLE_SIZE - 1)
#define NPTS 1048576
#define PRIME 2654435761u
#define THREADS 256
#define CG_LEVEL 12   // levels >= this use L2-only caching

struct ResArr { float r[LEVELS]; };

template <bool CG>
__device__ __forceinline__ float4 ld4(const float4* p) {
    return CG ? __ldcg(p) : __ldg(p);
}
template <bool CG>
__device__ __forceinline__ float2 ld2(const float2* p) {
    return CG ? __ldcg(p) : __ldg(p);
}

template <bool CG>
__device__ __forceinline__ void level_gather(
    const float2* __restrict__ t, float r, float px, float py,
    float& a0, float& a1)
{
    float sx = px * r;
    float sy = py * r;
    float gxf = floorf(sx);
    float gyf = floorf(sy);
    float fx = sx - gxf;          // weight factor for corner bx=0
    float fy = sy - gyf;
    float ox = 1.0f - fx;         // for bx=1
    float oy = 1.0f - fy;

    unsigned gx = (unsigned)(int)gxf;
    unsigned gy = (unsigned)(int)gyf;
    unsigned hy0 = gy * PRIME;
    unsigned hy1 = hy0 + PRIME;

    unsigned i00 = ( gx        ^ hy0) & HMASK;
    unsigned i01 = ( gx        ^ hy1) & HMASK;
    unsigned i10 = ((gx + 1u)  ^ hy0) & HMASK;
    unsigned i11 = ((gx + 1u)  ^ hy1) & HMASK;

    const float4* t4 = reinterpret_cast<const float4*>(t);
    float4 q0 = ld4<CG>(t4 + (i00 >> 1));   // entries {i00&~1, i00|1}
    float4 q1 = ld4<CG>(t4 + (i01 >> 1));   // entries {i01&~1, i01|1}

    bool hi0 = (i00 & 1u) != 0u;
    bool hi1 = (i01 & 1u) != 0u;

    float2 f00 = hi0 ? make_float2(q0.z, q0.w) : make_float2(q0.x, q0.y);
    float2 f01 = hi1 ? make_float2(q1.z, q1.w) : make_float2(q1.x, q1.y);
    // when gx even, the x+1 corner is the other half of the same pair
    float2 f10 = hi0 ? make_float2(q0.x, q0.y) : make_float2(q0.z, q0.w);
    float2 f11 = hi1 ? make_float2(q1.x, q1.y) : make_float2(q1.z, q1.w);

    if (gx & 1u) {                // odd: x+1 carries, pair trick invalid
        f10 = ld2<CG>(t + i10);
        f11 = ld2<CG>(t + i11);
    }

    float w00 = fx * fy;
    float w10 = ox * fy;
    float w01 = fx * oy;
    float w11 = ox * oy;

    a0 = (w00 * f00.x + w10 * f10.x) + (w01 * f01.x + w11 * f11.x);
    a1 = (w00 * f00.y + w10 * f10.y) + (w01 * f01.y + w11 * f11.y);
}

__global__ __launch_bounds__(THREADS)
void hashenc_kernel(const float* __restrict__ x,
                    const float2* __restrict__ tables,
                    float* __restrict__ out,
                    ResArr res)
{
    int n = blockIdx.x * blockDim.x + threadIdx.x;
    float2 p = reinterpret_cast<const float2*>(x)[n];

    float acc0[LEVELS];
    float acc1[LEVELS];

#pragma unroll
    for (int l = 0; l < LEVELS; ++l) {
        const float2* t = tables + (size_t)l * TABLE_SIZE;
        if (l >= CG_LEVEL)
            level_gather<true >(t, res.r[l], p.x, p.y, acc0[l], acc1[l]);
        else
            level_gather<false>(t, res.r[l], p.x, p.y, acc0[l], acc1[l]);
    }

    float4* o = reinterpret_cast<float4*>(out + (size_t)n * (2 * LEVELS));
#pragma unroll
    for (int i = 0; i < 4; ++i)
        o[i] = make_float4(acc0[4*i], acc0[4*i+1], acc0[4*i+2], acc0[4*i+3]);
#pragma unroll
    for (int i = 0; i < 4; ++i)
        o[4 + i] = make_float4(acc1[4*i], acc1[4*i+1], acc1[4*i+2], acc1[4*i+3]);
}

extern "C" void kernel_launch(void* const* d_in, const int* in_sizes, int n_in,
                              void* d_out, int out_size)
{
    // Exact float64 replication of the reference _RESOLUTIONS computation.
    ResArr res;
    double b = exp((log(512.0) - log(16.0)) / 15.0);
    for (int l = 0; l < LEVELS; ++l) {
        double pw;
        if (l == 0)      pw = 1.0;
        else if (l == 1) pw = b;
        else             pw = pow(b, (double)l);
        res.r[l] = (float)floor(16.0 * pw);
    }

    const float*  x      = (const float*)d_in[0];
    const float2* tables = (const float2*)d_in[1];
    float*        out    = (float*)d_out;

    hashenc_kernel<<<NPTS / THREADS, THREADS>>>(x, tables, out, res);
}